// round 13
// baseline (speedup 1.0000x reference)
#include <cuda_runtime.h>
#include <cuda_fp16.h>
#include <cuda_bf16.h>

#define NN   100000
#define EE   1600000
#define KDIN 128
#define DH   64
#define DOUT 32
#define NB_SCAN 98          // ceil(NN/1024)

// ---------------- scratch (static device globals; zero-initialized at load) ----------------
__device__ __align__(16) int    g_cnt   [NN];        // in-degree; re-zeroed by agg2_final
__device__ __align__(16) int    g_rows  [NN];
__device__ __align__(16) int    g_cursor[NN];
__device__ __align__(16) int    g_col   [EE];
__device__ __align__(16) int    g_bsum  [128];
__device__ __align__(16) float  g_dinv  [NN];
__device__ __align__(16) __half g_h1s   [NN * DH];   // (x@W1) * dinv[row], fp16
__device__ __align__(16) __half g_x1h   [NN * DH];   // relu'd layer-1 output, fp16
__device__ __align__(16) __half g_h2s   [NN * DOUT]; // (x1@W2) * dinv[row], fp16

// ---------------- CSR build ----------------
__global__ void hist_kernel(const int* __restrict__ dst) {
    int e = blockIdx.x * blockDim.x + threadIdx.x;
    if (e < EE) atomicAdd(&g_cnt[dst[e]], 1);
}

__global__ void dinv_kernel() {
    int i = blockIdx.x * blockDim.x + threadIdx.x;
    if (i < NN) g_dinv[i] = rsqrtf((float)g_cnt[i] + 1.0f);
}

__global__ void scan1_kernel() {
    __shared__ int wsum[8], woff[8];
    int tid = threadIdx.x, b = blockIdx.x;
    int lane = tid & 31, warp = tid >> 5;
    int base = b * 1024 + tid * 4;
    int v[4];
#pragma unroll
    for (int j = 0; j < 4; j++) v[j] = (base + j < NN) ? g_cnt[base + j] : 0;
    int ts = v[0] + v[1] + v[2] + v[3];
    int incl = ts;
#pragma unroll
    for (int o = 1; o < 32; o <<= 1) {
        int x = __shfl_up_sync(0xffffffffu, incl, o);
        if (lane >= o) incl += x;
    }
    int excl = incl - ts;
    if (lane == 31) wsum[warp] = incl;
    __syncthreads();
    if (tid == 0) {
        int r = 0;
#pragma unroll
        for (int w = 0; w < 8; w++) { woff[w] = r; r += wsum[w]; }
        g_bsum[b] = r;
    }
    __syncthreads();
    int off = woff[warp] + excl;
    int pre = 0;
#pragma unroll
    for (int j = 0; j < 4; j++) {
        if (base + j < NN) g_rows[base + j] = off + pre;
        pre += v[j];
    }
}

__global__ void scan3_kernel() {
    __shared__ int s_off;
    int tid = threadIdx.x;
    int chunk = (blockIdx.x * 256) >> 10;
    if (tid < 32) {
        int sum = 0;
        for (int j = tid; j < chunk; j += 32) sum += g_bsum[j];
#pragma unroll
        for (int o = 16; o > 0; o >>= 1) sum += __shfl_down_sync(0xffffffffu, sum, o);
        if (tid == 0) s_off = sum;
    }
    __syncthreads();
    int i = blockIdx.x * 256 + tid;
    if (i >= NN) return;
    int rs = g_rows[i] + s_off;
    g_rows[i] = rs;
    g_cursor[i] = rs;
}

__global__ void scatter_kernel(const int* __restrict__ src, const int* __restrict__ dst) {
    int e = blockIdx.x * blockDim.x + threadIdx.x;
    if (e >= EE) return;
    int d = dst[e];
    int p = atomicAdd(&g_cursor[d], 1);
    g_col[p] = src[e];
}

// ---------------- bf16x3 tensor-core GEMM ----------------
__device__ __forceinline__ void split2(float x0, float x1, unsigned& hi, unsigned& lo) {
    __nv_bfloat16 h0 = __float2bfloat16_rn(x0), h1 = __float2bfloat16_rn(x1);
    __nv_bfloat16 l0 = __float2bfloat16_rn(x0 - __bfloat162float(h0));
    __nv_bfloat16 l1 = __float2bfloat16_rn(x1 - __bfloat162float(h1));
    hi = ((unsigned)__bfloat16_as_ushort(h1) << 16) | __bfloat16_as_ushort(h0);
    lo = ((unsigned)__bfloat16_as_ushort(l1) << 16) | __bfloat16_as_ushort(l0);
}

__device__ __forceinline__ void mma16(float c[4], const unsigned a[4], const unsigned b[2]) {
    asm volatile("mma.sync.aligned.m16n8k16.row.col.f32.bf16.bf16.f32 "
                 "{%0,%1,%2,%3}, {%4,%5,%6,%7}, {%8,%9}, {%0,%1,%2,%3};"
                 : "+f"(c[0]), "+f"(c[1]), "+f"(c[2]), "+f"(c[3])
                 : "r"(a[0]), "r"(a[1]), "r"(a[2]), "r"(a[3]), "r"(b[0]), "r"(b[1]));
}

// C[r,:] = (A[r,:K] @ W[K,BN]) * dinv[r] -> fp16.  256 threads, warp = 16 rows.
// smem holds full K: interleaved bf16x2 (hi-pair, lo-pair) per k-pair, u32 pitch AP=K+4.
template<int BN, int K, bool HALF_IN>
__global__ void __launch_bounds__(256)
gemm_bf16x3(const void* __restrict__ Av, const float* __restrict__ W,
            const float* __restrict__ dinv, __half* __restrict__ C, int n) {
    constexpr int BM = 128;
    constexpr int AP = K + 4;           // u32 pitch: K/2 pairs * 2 (hi,lo) + pad
    constexpr int NTILES = BN / 8;
    extern __shared__ unsigned smem_u[];
    unsigned* sA = smem_u;              // [BM][AP]
    unsigned* sW = smem_u + BM * AP;    // [BN][AP]

    const int tid  = threadIdx.x;
    const int lane = tid & 31, warp = tid >> 5;
    const int g = lane >> 2, t = lane & 3;
    const int row0 = blockIdx.x * BM;
    const int wm = warp * 16;

    // stage W: transpose + bf16 hi/lo split, interleaved pairs
    for (int i = tid; i < (K / 2) * BN; i += 256) {
        int kp = i / BN, nn = i % BN;
        float w0 = W[(2 * kp) * BN + nn];
        float w1 = W[(2 * kp + 1) * BN + nn];
        unsigned hi, lo;
        split2(w0, w1, hi, lo);
        *reinterpret_cast<uint2*>(&sW[nn * AP + kp * 2]) = make_uint2(hi, lo);
    }
    // stage A: bf16 hi/lo split, 4 k-values per thread-iteration
    constexpr int K4 = K / 4;
    for (int i = tid; i < BM * K4; i += 256) {
        int r = i / K4, kq = i % K4;
        float4 v = {0.f, 0.f, 0.f, 0.f};
        if (row0 + r < n) {
            if (HALF_IN) {
                const __half* A = (const __half*)Av;
                uint2 u = *reinterpret_cast<const uint2*>(A + (size_t)(row0 + r) * K + kq * 4);
                float2 f0 = __half22float2(*reinterpret_cast<__half2*>(&u.x));
                float2 f1 = __half22float2(*reinterpret_cast<__half2*>(&u.y));
                v.x = f0.x; v.y = f0.y; v.z = f1.x; v.w = f1.y;
            } else {
                const float* A = (const float*)Av;
                v = *reinterpret_cast<const float4*>(A + (size_t)(row0 + r) * K + kq * 4);
            }
        }
        unsigned h0, l0, h1, l1;
        split2(v.x, v.y, h0, l0);
        split2(v.z, v.w, h1, l1);
        *reinterpret_cast<uint4*>(&sA[r * AP + kq * 4]) = make_uint4(h0, l0, h1, l1);
    }
    __syncthreads();

    float c[NTILES][4];
#pragma unroll
    for (int nt = 0; nt < NTILES; nt++)
#pragma unroll
        for (int j = 0; j < 4; j++) c[nt][j] = 0.f;

#pragma unroll
    for (int k0 = 0; k0 < K; k0 += 16) {
        const int ko = k0 + 2 * t;      // u32 offset of this lane's k-pair
        uint2 A0 = *reinterpret_cast<const uint2*>(&sA[(wm + g)     * AP + ko]);
        uint2 A1 = *reinterpret_cast<const uint2*>(&sA[(wm + g + 8) * AP + ko]);
        uint2 A2 = *reinterpret_cast<const uint2*>(&sA[(wm + g)     * AP + ko + 8]);
        uint2 A3 = *reinterpret_cast<const uint2*>(&sA[(wm + g + 8) * AP + ko + 8]);
        unsigned ah[4] = {A0.x, A1.x, A2.x, A3.x};
        unsigned al[4] = {A0.y, A1.y, A2.y, A3.y};
#pragma unroll
        for (int nt = 0; nt < NTILES; nt++) {
            const unsigned* pb = &sW[(nt * 8 + g) * AP + ko];
            uint2 B0 = *reinterpret_cast<const uint2*>(pb);
            uint2 B1 = *reinterpret_cast<const uint2*>(pb + 8);
            unsigned bh[2] = {B0.x, B1.x};
            unsigned bl[2] = {B0.y, B1.y};
            mma16(c[nt], ah, bh);
            mma16(c[nt], ah, bl);
            mma16(c[nt], al, bh);
        }
    }

    const int r0 = row0 + wm + g, r1 = r0 + 8;
    const float d0 = (r0 < n) ? dinv[r0] : 0.f;
    const float d1 = (r1 < n) ? dinv[r1] : 0.f;
#pragma unroll
    for (int nt = 0; nt < NTILES; nt++) {
        const int colb = nt * 8 + 2 * t;
        if (r0 < n)
            *reinterpret_cast<__half2*>(&C[(size_t)r0 * BN + colb]) =
                __floats2half2_rn(c[nt][0] * d0, c[nt][1] * d0);
        if (r1 < n)
            *reinterpret_cast<__half2*>(&C[(size_t)r1 * BN + colb]) =
                __floats2half2_rn(c[nt][2] * d1, c[nt][3] * d1);
    }
}

// ---------------- layer-1 aggregation: warp/node, lane = half2 channel pair ----------------
__global__ void agg1_kernel(const float* __restrict__ b1) {
    int node = blockIdx.x * 8 + (threadIdx.x >> 5);
    int lane = threadIdx.x & 31;
    if (node >= NN) return;
    int beg = g_rows[node], cnt = g_cnt[node];
    const __half2* __restrict__ h = reinterpret_cast<const __half2*>(g_h1s);
    float2 acc = {0.f, 0.f};
    int j = 0;
    for (; j + 4 <= cnt; j += 4) {
        int s0 = g_col[beg + j], s1 = g_col[beg + j + 1];
        int s2 = g_col[beg + j + 2], s3 = g_col[beg + j + 3];
        float2 v0 = __half22float2(h[s0 * 32 + lane]);
        float2 v1 = __half22float2(h[s1 * 32 + lane]);
        float2 v2 = __half22float2(h[s2 * 32 + lane]);
        float2 v3 = __half22float2(h[s3 * 32 + lane]);
        acc.x += (v0.x + v1.x) + (v2.x + v3.x);
        acc.y += (v0.y + v1.y) + (v2.y + v3.y);
    }
    for (; j < cnt; j++) {
        float2 v = __half22float2(h[g_col[beg + j] * 32 + lane]);
        acc.x += v.x; acc.y += v.y;
    }
    float di = g_dinv[node];
    float2 self = __half22float2(h[node * 32 + lane]);
    float2 bb = reinterpret_cast<const float2*>(b1)[lane];
    float ox = fmaxf(fmaf(di, acc.x + self.x, bb.x), 0.f);
    float oy = fmaxf(fmaf(di, acc.y + self.y, bb.y), 0.f);
    reinterpret_cast<__half2*>(g_x1h)[node * 32 + lane] = __floats2half2_rn(ox, oy);
}

// ---------------- layer-2 agg + scorer: 2 nodes/warp; re-zeroes g_cnt for next replay ----------------
__global__ void agg2_final_kernel(const float* __restrict__ b2, const float* __restrict__ fcw,
                                  const float* __restrict__ fcb, float* __restrict__ out) {
    int warp = blockIdx.x * 8 + (threadIdx.x >> 5);
    int lane = threadIdx.x & 31;
    int half = lane >> 4;
    int hl   = lane & 15;
    int node = warp * 2 + half;
    if (node >= NN) return;
    int beg = g_rows[node], cnt = g_cnt[node];
    const __half2* __restrict__ h = reinterpret_cast<const __half2*>(g_h2s);
    float2 acc = {0.f, 0.f};
    int j = 0;
    for (; j + 4 <= cnt; j += 4) {
        int s0 = g_col[beg + j], s1 = g_col[beg + j + 1];
        int s2 = g_col[beg + j + 2], s3 = g_col[beg + j + 3];
        float2 v0 = __half22float2(h[s0 * 16 + hl]);
        float2 v1 = __half22float2(h[s1 * 16 + hl]);
        float2 v2 = __half22float2(h[s2 * 16 + hl]);
        float2 v3 = __half22float2(h[s3 * 16 + hl]);
        acc.x += (v0.x + v1.x) + (v2.x + v3.x);
        acc.y += (v0.y + v1.y) + (v2.y + v3.y);
    }
    for (; j < cnt; j++) {
        float2 v = __half22float2(h[g_col[beg + j] * 16 + hl]);
        acc.x += v.x; acc.y += v.y;
    }
    float di = g_dinv[node];
    float2 self = __half22float2(h[node * 16 + hl]);
    float2 bb = reinterpret_cast<const float2*>(b2)[hl];
    float2 o;
    o.x = fmaxf(fmaf(di, acc.x + self.x, bb.x), 0.f);
    o.y = fmaxf(fmaf(di, acc.y + self.y, bb.y), 0.f);
    reinterpret_cast<float2*>(out + NN)[node * 16 + hl] = o;
    float2 fw = reinterpret_cast<const float2*>(fcw)[hl];
    float s = o.x * fw.x + o.y * fw.y;
#pragma unroll
    for (int off = 8; off > 0; off >>= 1)
        s += __shfl_down_sync(0xffffffffu, s, off, 16);
    if (hl == 0) {
        out[node] = s + fcb[0];
        g_cnt[node] = 0;            // restore invariant for next graph replay
    }
}

// ---------------- launch ----------------
extern "C" void kernel_launch(void* const* d_in, const int* in_sizes, int n_in,
                              void* d_out, int out_size) {
    const float* x   = (const float*)d_in[0];
    const int*   ei  = (const int*)  d_in[1];
    const float* W1  = (const float*)d_in[2];
    const float* b1  = (const float*)d_in[3];
    const float* W2  = (const float*)d_in[4];
    const float* b2  = (const float*)d_in[5];
    const float* fcw = (const float*)d_in[6];
    const float* fcb = (const float*)d_in[7];
    float* out = (float*)d_out;

    const int* src = ei;
    const int* dst = ei + EE;

    __half *h1s, *h2s, *x1h;
    float *dinv;
    cudaGetSymbolAddress((void**)&h1s,  g_h1s);
    cudaGetSymbolAddress((void**)&x1h,  g_x1h);
    cudaGetSymbolAddress((void**)&h2s,  g_h2s);
    cudaGetSymbolAddress((void**)&dinv, g_dinv);

    static cudaStream_t s2 = [] { cudaStream_t s; cudaStreamCreateWithFlags(&s, cudaStreamNonBlocking); return s; }();
    static cudaEvent_t evH = [] { cudaEvent_t e; cudaEventCreateWithFlags(&e, cudaEventDisableTiming); return e; }();
    static cudaEvent_t evC = [] { cudaEvent_t e; cudaEventCreateWithFlags(&e, cudaEventDisableTiming); return e; }();

    // ---- main stream: hist -> dinv -> GEMM1 ----
    hist_kernel<<<(EE + 511) / 512, 512>>>(dst);
    cudaEventRecord(evH, 0);
    dinv_kernel<<<(NN + 255) / 256, 256>>>();

    constexpr int SM1 = (128 * (KDIN + 4) + DH * (KDIN + 4)) * 4;   // 101376 B
    cudaFuncSetAttribute((const void*)gemm_bf16x3<DH, KDIN, false>,
                         cudaFuncAttributeMaxDynamicSharedMemorySize, SM1);
    gemm_bf16x3<DH, KDIN, false><<<(NN + 127) / 128, 256, SM1>>>(x, W1, dinv, h1s, NN);

    // ---- side stream (forked after hist): scan1 -> scan3 -> scatter ----
    cudaStreamWaitEvent(s2, evH, 0);
    scan1_kernel<<<NB_SCAN, 256, 0, s2>>>();
    scan3_kernel<<<(NN + 255) / 256, 256, 0, s2>>>();
    scatter_kernel<<<(EE + 511) / 512, 512, 0, s2>>>(src, dst);
    cudaEventRecord(evC, s2);

    // ---- join, then agg1 -> GEMM2 -> agg2 ----
    cudaStreamWaitEvent(0, evC, 0);
    agg1_kernel<<<(NN + 7) / 8, 256>>>(b1);

    constexpr int SM2 = (128 * (DH + 4) + DOUT * (DH + 4)) * 4;     // 43520 B
    cudaFuncSetAttribute((const void*)gemm_bf16x3<DOUT, DH, true>,
                         cudaFuncAttributeMaxDynamicSharedMemorySize, SM2);
    gemm_bf16x3<DOUT, DH, true><<<(NN + 127) / 128, 256, SM2>>>(x1h, W2, dinv, h2s, NN);
    agg2_final_kernel<<<(NN + 15) / 16, 256>>>(b2, fcw, fcb, out);
    (void)in_sizes; (void)n_in; (void)out_size;
}

// round 15
// speedup vs baseline: 1.0431x; 1.0431x over previous
#include <cuda_runtime.h>
#include <cuda_fp16.h>

#define NN   100000
#define EE   1600000
#define KDIN 128
#define DH   64
#define DOUT 32
#define NB_SCAN 98          // ceil(NN/1024)

// ---------------- scratch (static device globals; zero-initialized at load) ----------------
__device__ __align__(16) int    g_cnt   [NN];        // in-degree; re-zeroed by agg2_final
__device__ __align__(16) int    g_rows  [NN];
__device__ __align__(16) int    g_cursor[NN];
__device__ __align__(16) int    g_col   [EE];
__device__ __align__(16) int    g_bsum  [128];
__device__ __align__(16) float  g_dinv  [NN];
__device__ __align__(16) __half g_h1s   [NN * DH];   // x@W1 (UNscaled), fp16
__device__ __align__(16) __half g_x1h   [NN * DH];   // relu'd layer-1 output, fp16
__device__ __align__(16) __half g_h2s   [NN * DOUT]; // (x1@W2) * dinv[row], fp16

// ---------------- CSR build (side stream) ----------------
__global__ void hist_kernel(const int* __restrict__ dst) {
    int e = blockIdx.x * blockDim.x + threadIdx.x;
    if (e < EE) atomicAdd(&g_cnt[dst[e]], 1);
}

__global__ void scan1_kernel() {
    __shared__ int wsum[8], woff[8];
    int tid = threadIdx.x, b = blockIdx.x;
    int lane = tid & 31, warp = tid >> 5;
    int base = b * 1024 + tid * 4;
    int v[4];
#pragma unroll
    for (int j = 0; j < 4; j++) v[j] = (base + j < NN) ? g_cnt[base + j] : 0;
    int ts = v[0] + v[1] + v[2] + v[3];
    int incl = ts;
#pragma unroll
    for (int o = 1; o < 32; o <<= 1) {
        int x = __shfl_up_sync(0xffffffffu, incl, o);
        if (lane >= o) incl += x;
    }
    int excl = incl - ts;
    if (lane == 31) wsum[warp] = incl;
    __syncthreads();
    if (tid == 0) {
        int r = 0;
#pragma unroll
        for (int w = 0; w < 8; w++) { woff[w] = r; r += wsum[w]; }
        g_bsum[b] = r;
    }
    __syncthreads();
    int off = woff[warp] + excl;
    int pre = 0;
#pragma unroll
    for (int j = 0; j < 4; j++) {
        if (base + j < NN) g_rows[base + j] = off + pre;
        pre += v[j];
    }
}

// finalize row offsets + cursors + dinv (all off the critical path)
__global__ void scan3_kernel() {
    __shared__ int s_off;
    int tid = threadIdx.x;
    int chunk = (blockIdx.x * 256) >> 10;
    if (tid < 32) {
        int sum = 0;
        for (int j = tid; j < chunk; j += 32) sum += g_bsum[j];
#pragma unroll
        for (int o = 16; o > 0; o >>= 1) sum += __shfl_down_sync(0xffffffffu, sum, o);
        if (tid == 0) s_off = sum;
    }
    __syncthreads();
    int i = blockIdx.x * 256 + tid;
    if (i >= NN) return;
    int rs = g_rows[i] + s_off;
    g_rows[i] = rs;
    g_cursor[i] = rs;
    g_dinv[i] = rsqrtf((float)g_cnt[i] + 1.0f);
}

__global__ void scatter_kernel(const int* __restrict__ src, const int* __restrict__ dst) {
    int e = blockIdx.x * blockDim.x + threadIdx.x;
    if (e >= EE) return;
    int d = dst[e];
    int p = atomicAdd(&g_cursor[d], 1);
    g_col[p] = src[e];
}

// ---------------- tf32x3 tensor-core GEMM (proven R8 design) ----------------
__device__ __forceinline__ float tf32_hi(float x) {
    unsigned u;
    asm("cvt.rna.tf32.f32 %0, %1;" : "=r"(u) : "f"(x));
    return __uint_as_float(u);
}

__device__ __forceinline__ void mma8(float c[4], const unsigned a[4], const unsigned b[2]) {
    asm volatile("mma.sync.aligned.m16n8k8.row.col.f32.tf32.tf32.f32 "
                 "{%0,%1,%2,%3}, {%4,%5,%6,%7}, {%8,%9}, {%0,%1,%2,%3};"
                 : "+f"(c[0]), "+f"(c[1]), "+f"(c[2]), "+f"(c[3])
                 : "r"(a[0]), "r"(a[1]), "r"(a[2]), "r"(a[3]), "r"(b[0]), "r"(b[1]));
}

// C[r,:] = (A[r,:K] @ W[K,BN]) [* dinv[r] if SCALE] -> fp16.  256 threads, warp = 16 rows.
template<int BN, int K, bool HALF_IN, bool SCALE>
__global__ void __launch_bounds__(256)
gemm_mma(const void* __restrict__ Av, const float* __restrict__ W,
         const float* __restrict__ dinv, __half* __restrict__ C, int n) {
    constexpr int BM = 128;
    constexpr int KT = 64;
    constexpr int KP = KT + 4;
    constexpr int WP = K + 4;
    constexpr int NTILES = BN / 8;
    extern __shared__ float smem[];
    float* As = smem;                   // [BM][KP]
    float* Wh = smem + BM * KP;         // [BN][WP]
    float* Wl = Wh + BN * WP;

    const int tid  = threadIdx.x;
    const int lane = tid & 31, warp = tid >> 5;
    const int g = lane >> 2, t = lane & 3;
    const int row0 = blockIdx.x * BM;
    const int wm = warp * 16;

    for (int i = tid; i < K * BN; i += 256) {
        int k = i / BN, nn = i % BN;
        float w = W[i];
        float h = tf32_hi(w);
        Wh[nn * WP + k] = h;
        Wl[nn * WP + k] = tf32_hi(w - h);
    }

    float c[NTILES][4];
#pragma unroll
    for (int nt = 0; nt < NTILES; nt++)
#pragma unroll
        for (int j = 0; j < 4; j++) c[nt][j] = 0.f;

    for (int kt = 0; kt < K; kt += KT) {
        if (kt) __syncthreads();
        constexpr int KT4 = KT / 4;
        for (int i = tid; i < BM * KT4; i += 256) {
            int r = i / KT4, kq = i % KT4;
            float4 v = {0.f, 0.f, 0.f, 0.f};
            if (row0 + r < n) {
                if (HALF_IN) {
                    const __half* A = (const __half*)Av;
                    uint2 u = *reinterpret_cast<const uint2*>(A + (size_t)(row0 + r) * K + kt + kq * 4);
                    float2 f0 = __half22float2(*reinterpret_cast<__half2*>(&u.x));
                    float2 f1 = __half22float2(*reinterpret_cast<__half2*>(&u.y));
                    v.x = f0.x; v.y = f0.y; v.z = f1.x; v.w = f1.y;
                } else {
                    const float* A = (const float*)Av;
                    v = *reinterpret_cast<const float4*>(A + (size_t)(row0 + r) * K + kt + kq * 4);
                }
            }
            *reinterpret_cast<float4*>(As + r * KP + kq * 4) = v;
        }
        __syncthreads();

#pragma unroll
        for (int k0 = 0; k0 < KT; k0 += 8) {
            float a[4];
            a[0] = As[(wm + g)     * KP + k0 + t];
            a[1] = As[(wm + g + 8) * KP + k0 + t];
            a[2] = As[(wm + g)     * KP + k0 + t + 4];
            a[3] = As[(wm + g + 8) * KP + k0 + t + 4];
            unsigned ah[4], al[4];
#pragma unroll
            for (int j = 0; j < 4; j++) {
                float h = tf32_hi(a[j]);
                ah[j] = __float_as_uint(h);
                al[j] = __float_as_uint(tf32_hi(a[j] - h));
            }
            const int kg = kt + k0;
#pragma unroll
            for (int nt = 0; nt < NTILES; nt++) {
                const int wr = (nt * 8 + g) * WP + kg + t;
                unsigned bh[2], bl[2];
                bh[0] = __float_as_uint(Wh[wr]);
                bh[1] = __float_as_uint(Wh[wr + 4]);
                bl[0] = __float_as_uint(Wl[wr]);
                bl[1] = __float_as_uint(Wl[wr + 4]);
                mma8(c[nt], ah, bh);
                mma8(c[nt], ah, bl);
                mma8(c[nt], al, bh);
            }
        }
    }

    const int r0 = row0 + wm + g, r1 = r0 + 8;
    const float d0 = SCALE ? ((r0 < n) ? dinv[r0] : 0.f) : 1.f;
    const float d1 = SCALE ? ((r1 < n) ? dinv[r1] : 0.f) : 1.f;
#pragma unroll
    for (int nt = 0; nt < NTILES; nt++) {
        const int colb = nt * 8 + 2 * t;
        if (r0 < n)
            *reinterpret_cast<__half2*>(&C[(size_t)r0 * BN + colb]) =
                __floats2half2_rn(c[nt][0] * d0, c[nt][1] * d0);
        if (r1 < n)
            *reinterpret_cast<__half2*>(&C[(size_t)r1 * BN + colb]) =
                __floats2half2_rn(c[nt][2] * d1, c[nt][3] * d1);
    }
}

// ---------------- layer-1 aggregation: warp/node; dinv[src] applied at gather ----------------
__global__ void agg1_kernel(const float* __restrict__ b1) {
    int node = blockIdx.x * 8 + (threadIdx.x >> 5);
    int lane = threadIdx.x & 31;
    if (node >= NN) return;
    int beg = g_rows[node], cnt = g_cnt[node];
    const __half2* __restrict__ h = reinterpret_cast<const __half2*>(g_h1s);
    float2 acc = {0.f, 0.f};
    int j = 0;
    for (; j + 4 <= cnt; j += 4) {
        int s0 = g_col[beg + j], s1 = g_col[beg + j + 1];
        int s2 = g_col[beg + j + 2], s3 = g_col[beg + j + 3];
        float d0 = g_dinv[s0], d1 = g_dinv[s1], d2 = g_dinv[s2], d3 = g_dinv[s3];
        float2 v0 = __half22float2(h[s0 * 32 + lane]);
        float2 v1 = __half22float2(h[s1 * 32 + lane]);
        float2 v2 = __half22float2(h[s2 * 32 + lane]);
        float2 v3 = __half22float2(h[s3 * 32 + lane]);
        acc.x = fmaf(v0.x, d0, fmaf(v1.x, d1, fmaf(v2.x, d2, fmaf(v3.x, d3, acc.x))));
        acc.y = fmaf(v0.y, d0, fmaf(v1.y, d1, fmaf(v2.y, d2, fmaf(v3.y, d3, acc.y))));
    }
    for (; j < cnt; j++) {
        int s = g_col[beg + j];
        float ds = g_dinv[s];
        float2 v = __half22float2(h[s * 32 + lane]);
        acc.x = fmaf(v.x, ds, acc.x);
        acc.y = fmaf(v.y, ds, acc.y);
    }
    float di = g_dinv[node];
    float2 self = __half22float2(h[node * 32 + lane]);
    float2 bb = reinterpret_cast<const float2*>(b1)[lane];
    float ox = fmaxf(fmaf(di, fmaf(di, self.x, acc.x), bb.x), 0.f);
    float oy = fmaxf(fmaf(di, fmaf(di, self.y, acc.y), bb.y), 0.f);
    reinterpret_cast<__half2*>(g_x1h)[node * 32 + lane] = __floats2half2_rn(ox, oy);
}

// ---------------- layer-2 agg + scorer: 2 nodes/warp; re-zeroes g_cnt for next replay ----------------
__global__ void agg2_final_kernel(const float* __restrict__ b2, const float* __restrict__ fcw,
                                  const float* __restrict__ fcb, float* __restrict__ out) {
    int warp = blockIdx.x * 8 + (threadIdx.x >> 5);
    int lane = threadIdx.x & 31;
    int half = lane >> 4;
    int hl   = lane & 15;
    int node = warp * 2 + half;
    if (node >= NN) return;
    int beg = g_rows[node], cnt = g_cnt[node];
    const __half2* __restrict__ h = reinterpret_cast<const __half2*>(g_h2s);
    float2 acc = {0.f, 0.f};
    int j = 0;
    for (; j + 4 <= cnt; j += 4) {
        int s0 = g_col[beg + j], s1 = g_col[beg + j + 1];
        int s2 = g_col[beg + j + 2], s3 = g_col[beg + j + 3];
        float2 v0 = __half22float2(h[s0 * 16 + hl]);
        float2 v1 = __half22float2(h[s1 * 16 + hl]);
        float2 v2 = __half22float2(h[s2 * 16 + hl]);
        float2 v3 = __half22float2(h[s3 * 16 + hl]);
        acc.x += (v0.x + v1.x) + (v2.x + v3.x);
        acc.y += (v0.y + v1.y) + (v2.y + v3.y);
    }
    for (; j < cnt; j++) {
        float2 v = __half22float2(h[g_col[beg + j] * 16 + hl]);
        acc.x += v.x; acc.y += v.y;
    }
    float di = g_dinv[node];
    float2 self = __half22float2(h[node * 16 + hl]);
    float2 bb = reinterpret_cast<const float2*>(b2)[hl];
    float2 o;
    o.x = fmaxf(fmaf(di, acc.x + self.x, bb.x), 0.f);
    o.y = fmaxf(fmaf(di, acc.y + self.y, bb.y), 0.f);
    reinterpret_cast<float2*>(out + NN)[node * 16 + hl] = o;
    float2 fw = reinterpret_cast<const float2*>(fcw)[hl];
    float s = o.x * fw.x + o.y * fw.y;
#pragma unroll
    for (int off = 8; off > 0; off >>= 1)
        s += __shfl_down_sync(0xffffffffu, s, off, 16);
    if (hl == 0) {
        out[node] = s + fcb[0];
        g_cnt[node] = 0;            // restore invariant for next graph replay
    }
}

// ---------------- launch ----------------
extern "C" void kernel_launch(void* const* d_in, const int* in_sizes, int n_in,
                              void* d_out, int out_size) {
    const float* x   = (const float*)d_in[0];
    const int*   ei  = (const int*)  d_in[1];
    const float* W1  = (const float*)d_in[2];
    const float* b1  = (const float*)d_in[3];
    const float* W2  = (const float*)d_in[4];
    const float* b2  = (const float*)d_in[5];
    const float* fcw = (const float*)d_in[6];
    const float* fcb = (const float*)d_in[7];
    float* out = (float*)d_out;

    const int* src = ei;
    const int* dst = ei + EE;

    __half *h1s, *h2s, *x1h;
    float *dinv;
    cudaGetSymbolAddress((void**)&h1s,  g_h1s);
    cudaGetSymbolAddress((void**)&x1h,  g_x1h);
    cudaGetSymbolAddress((void**)&h2s,  g_h2s);
    cudaGetSymbolAddress((void**)&dinv, g_dinv);

    static cudaStream_t s2 = [] { cudaStream_t s; cudaStreamCreateWithFlags(&s, cudaStreamNonBlocking); return s; }();
    static cudaEvent_t evF = [] { cudaEvent_t e; cudaEventCreateWithFlags(&e, cudaEventDisableTiming); return e; }();
    static cudaEvent_t evC = [] { cudaEvent_t e; cudaEventCreateWithFlags(&e, cudaEventDisableTiming); return e; }();

    // fork: side stream builds the ENTIRE CSR (hist -> scan1 -> scan3(+dinv) -> scatter)
    cudaEventRecord(evF, 0);
    cudaStreamWaitEvent(s2, evF, 0);
    hist_kernel<<<(EE + 511) / 512, 512, 0, s2>>>(dst);
    scan1_kernel<<<NB_SCAN, 256, 0, s2>>>();
    scan3_kernel<<<(NN + 255) / 256, 256, 0, s2>>>();
    scatter_kernel<<<(EE + 511) / 512, 512, 0, s2>>>(src, dst);
    cudaEventRecord(evC, s2);

    // main stream: GEMM1 (unscaled, no dependencies) runs concurrently with CSR build
    constexpr int SM1 = (128 * 68 + 2 * DH * (KDIN + 4)) * 4;
    cudaFuncSetAttribute((const void*)gemm_mma<DH, KDIN, false, false>,
                         cudaFuncAttributeMaxDynamicSharedMemorySize, SM1);
    gemm_mma<DH, KDIN, false, false><<<(NN + 127) / 128, 256, SM1>>>(x, W1, nullptr, h1s, NN);

    // join, then agg1 -> GEMM2 -> agg2
    cudaStreamWaitEvent(0, evC, 0);
    agg1_kernel<<<(NN + 7) / 8, 256>>>(b1);

    constexpr int SM2 = (128 * 68 + 2 * DOUT * (DH + 4)) * 4;
    cudaFuncSetAttribute((const void*)gemm_mma<DOUT, DH, true, true>,
                         cudaFuncAttributeMaxDynamicSharedMemorySize, SM2);
    gemm_mma<DOUT, DH, true, true><<<(NN + 127) / 128, 256, SM2>>>(x1h, W2, dinv, h2s, NN);
    agg2_final_kernel<<<(NN + 15) / 16, 256>>>(b2, fcw, fcb, out);
    (void)in_sizes; (void)n_in; (void)out_size;
}

// round 16
// speedup vs baseline: 1.1049x; 1.0592x over previous
#include <cuda_runtime.h>
#include <cuda_fp16.h>

#define NN   100000
#define EE   1600000
#define KDIN 128
#define DH   64
#define DOUT 32
#define NB_SCAN 98          // ceil(NN/1024)

// ---------------- scratch (static device globals; zero-initialized at load) ----------------
__device__ __align__(16) int    g_cnt   [NN];        // in-degree; re-zeroed by agg2_final
__device__ __align__(16) int    g_rows  [NN];
__device__ __align__(16) int    g_rank  [EE];        // per-edge rank within its dst
__device__ __align__(16) int    g_col   [EE];        // CSR column (src) indices
__device__ __align__(16) int    g_bsum  [128];
__device__ __align__(16) float  g_dinv  [NN];
__device__ __align__(16) __half g_h1s   [NN * DH];   // (x@W1) * dinv[row], fp16
__device__ __align__(16) __half g_x1h   [NN * DH];   // relu'd layer-1 output, fp16
__device__ __align__(16) __half g_h2s   [NN * DOUT]; // (x1@W2) * dinv[row], fp16

// ---------------- CSR build ----------------
// hist also records each edge's arrival rank -> scatter needs no atomics.
__global__ void hist_kernel(const int* __restrict__ dst) {
    int e = blockIdx.x * blockDim.x + threadIdx.x;
    if (e < EE) g_rank[e] = atomicAdd(&g_cnt[dst[e]], 1);
}

__global__ void dinv_kernel() {
    int i = blockIdx.x * blockDim.x + threadIdx.x;
    if (i < NN) g_dinv[i] = rsqrtf((float)g_cnt[i] + 1.0f);
}

__global__ void scan1_kernel() {
    __shared__ int wsum[8], woff[8];
    int tid = threadIdx.x, b = blockIdx.x;
    int lane = tid & 31, warp = tid >> 5;
    int base = b * 1024 + tid * 4;
    int v[4];
#pragma unroll
    for (int j = 0; j < 4; j++) v[j] = (base + j < NN) ? g_cnt[base + j] : 0;
    int ts = v[0] + v[1] + v[2] + v[3];
    int incl = ts;
#pragma unroll
    for (int o = 1; o < 32; o <<= 1) {
        int x = __shfl_up_sync(0xffffffffu, incl, o);
        if (lane >= o) incl += x;
    }
    int excl = incl - ts;
    if (lane == 31) wsum[warp] = incl;
    __syncthreads();
    if (tid == 0) {
        int r = 0;
#pragma unroll
        for (int w = 0; w < 8; w++) { woff[w] = r; r += wsum[w]; }
        g_bsum[b] = r;
    }
    __syncthreads();
    int off = woff[warp] + excl;
    int pre = 0;
#pragma unroll
    for (int j = 0; j < 4; j++) {
        if (base + j < NN) g_rows[base + j] = off + pre;
        pre += v[j];
    }
}

__global__ void scan3_kernel() {
    __shared__ int s_off;
    int tid = threadIdx.x;
    int chunk = (blockIdx.x * 256) >> 10;
    if (tid < 32) {
        int sum = 0;
        for (int j = tid; j < chunk; j += 32) sum += g_bsum[j];
#pragma unroll
        for (int o = 16; o > 0; o >>= 1) sum += __shfl_down_sync(0xffffffffu, sum, o);
        if (tid == 0) s_off = sum;
    }
    __syncthreads();
    int i = blockIdx.x * 256 + tid;
    if (i >= NN) return;
    g_rows[i] = g_rows[i] + s_off;
}

// atomic-free scatter: position = rows[dst] + rank (unique per edge)
__global__ void scatter_kernel(const int* __restrict__ src, const int* __restrict__ dst) {
    int e = blockIdx.x * blockDim.x + threadIdx.x;
    if (e >= EE) return;
    g_col[g_rows[dst[e]] + g_rank[e]] = src[e];
}

// ---------------- tf32x3 tensor-core GEMM ----------------
__device__ __forceinline__ float tf32_hi(float x) {
    unsigned u;
    asm("cvt.rna.tf32.f32 %0, %1;" : "=r"(u) : "f"(x));
    return __uint_as_float(u);
}

__device__ __forceinline__ void mma8(float c[4], const unsigned a[4], const unsigned b[2]) {
    asm volatile("mma.sync.aligned.m16n8k8.row.col.f32.tf32.tf32.f32 "
                 "{%0,%1,%2,%3}, {%4,%5,%6,%7}, {%8,%9}, {%0,%1,%2,%3};"
                 : "+f"(c[0]), "+f"(c[1]), "+f"(c[2]), "+f"(c[3])
                 : "r"(a[0]), "r"(a[1]), "r"(a[2]), "r"(a[3]), "r"(b[0]), "r"(b[1]));
}

// C[r,:] = (A[r,:K] @ W[K,BN]) * dinv[r] -> fp16.  256 threads, warp = 16 rows.
template<int BN, int K, bool HALF_IN>
__global__ void __launch_bounds__(256)
gemm_mma(const void* __restrict__ Av, const float* __restrict__ W,
         const float* __restrict__ dinv, __half* __restrict__ C, int n) {
    constexpr int BM = 128;
    constexpr int KT = 64;
    constexpr int KP = KT + 4;
    constexpr int WP = K + 4;
    constexpr int NTILES = BN / 8;
    extern __shared__ float smem[];
    float* As = smem;                   // [BM][KP]
    float* Wh = smem + BM * KP;         // [BN][WP]
    float* Wl = Wh + BN * WP;

    const int tid  = threadIdx.x;
    const int lane = tid & 31, warp = tid >> 5;
    const int g = lane >> 2, t = lane & 3;
    const int row0 = blockIdx.x * BM;
    const int wm = warp * 16;

    for (int i = tid; i < K * BN; i += 256) {
        int k = i / BN, nn = i % BN;
        float w = W[i];
        float h = tf32_hi(w);
        Wh[nn * WP + k] = h;
        Wl[nn * WP + k] = tf32_hi(w - h);
    }

    float c[NTILES][4];
#pragma unroll
    for (int nt = 0; nt < NTILES; nt++)
#pragma unroll
        for (int j = 0; j < 4; j++) c[nt][j] = 0.f;

    for (int kt = 0; kt < K; kt += KT) {
        if (kt) __syncthreads();
        constexpr int KT4 = KT / 4;
        for (int i = tid; i < BM * KT4; i += 256) {
            int r = i / KT4, kq = i % KT4;
            float4 v = {0.f, 0.f, 0.f, 0.f};
            if (row0 + r < n) {
                if (HALF_IN) {
                    const __half* A = (const __half*)Av;
                    uint2 u = *reinterpret_cast<const uint2*>(A + (size_t)(row0 + r) * K + kt + kq * 4);
                    float2 f0 = __half22float2(*reinterpret_cast<__half2*>(&u.x));
                    float2 f1 = __half22float2(*reinterpret_cast<__half2*>(&u.y));
                    v.x = f0.x; v.y = f0.y; v.z = f1.x; v.w = f1.y;
                } else {
                    const float* A = (const float*)Av;
                    v = *reinterpret_cast<const float4*>(A + (size_t)(row0 + r) * K + kt + kq * 4);
                }
            }
            *reinterpret_cast<float4*>(As + r * KP + kq * 4) = v;
        }
        __syncthreads();

#pragma unroll
        for (int k0 = 0; k0 < KT; k0 += 8) {
            float a[4];
            a[0] = As[(wm + g)     * KP + k0 + t];
            a[1] = As[(wm + g + 8) * KP + k0 + t];
            a[2] = As[(wm + g)     * KP + k0 + t + 4];
            a[3] = As[(wm + g + 8) * KP + k0 + t + 4];
            unsigned ah[4], al[4];
#pragma unroll
            for (int j = 0; j < 4; j++) {
                float h = tf32_hi(a[j]);
                ah[j] = __float_as_uint(h);
                al[j] = __float_as_uint(tf32_hi(a[j] - h));
            }
            const int kg = kt + k0;
#pragma unroll
            for (int nt = 0; nt < NTILES; nt++) {
                const int wr = (nt * 8 + g) * WP + kg + t;
                unsigned bh[2], bl[2];
                bh[0] = __float_as_uint(Wh[wr]);
                bh[1] = __float_as_uint(Wh[wr + 4]);
                bl[0] = __float_as_uint(Wl[wr]);
                bl[1] = __float_as_uint(Wl[wr + 4]);
                mma8(c[nt], ah, bh);
                mma8(c[nt], ah, bl);
                mma8(c[nt], al, bh);
            }
        }
    }

    const int r0 = row0 + wm + g, r1 = r0 + 8;
    const float d0 = (r0 < n) ? dinv[r0] : 0.f;
    const float d1 = (r1 < n) ? dinv[r1] : 0.f;
#pragma unroll
    for (int nt = 0; nt < NTILES; nt++) {
        const int colb = nt * 8 + 2 * t;
        if (r0 < n)
            *reinterpret_cast<__half2*>(&C[(size_t)r0 * BN + colb]) =
                __floats2half2_rn(c[nt][0] * d0, c[nt][1] * d0);
        if (r1 < n)
            *reinterpret_cast<__half2*>(&C[(size_t)r1 * BN + colb]) =
                __floats2half2_rn(c[nt][2] * d1, c[nt][3] * d1);
    }
}

// ---------------- layer-1 aggregation: warp/node, lane = half2 channel pair ----------------
__global__ void agg1_kernel(const float* __restrict__ b1) {
    int node = blockIdx.x * 8 + (threadIdx.x >> 5);
    int lane = threadIdx.x & 31;
    if (node >= NN) return;
    int beg = g_rows[node], cnt = g_cnt[node];
    const __half2* __restrict__ h = reinterpret_cast<const __half2*>(g_h1s);
    float2 acc = {0.f, 0.f};
    int j = 0;
    for (; j + 4 <= cnt; j += 4) {
        int s0 = g_col[beg + j], s1 = g_col[beg + j + 1];
        int s2 = g_col[beg + j + 2], s3 = g_col[beg + j + 3];
        float2 v0 = __half22float2(h[s0 * 32 + lane]);
        float2 v1 = __half22float2(h[s1 * 32 + lane]);
        float2 v2 = __half22float2(h[s2 * 32 + lane]);
        float2 v3 = __half22float2(h[s3 * 32 + lane]);
        acc.x += (v0.x + v1.x) + (v2.x + v3.x);
        acc.y += (v0.y + v1.y) + (v2.y + v3.y);
    }
    for (; j < cnt; j++) {
        float2 v = __half22float2(h[g_col[beg + j] * 32 + lane]);
        acc.x += v.x; acc.y += v.y;
    }
    float di = g_dinv[node];
    float2 self = __half22float2(h[node * 32 + lane]);
    float2 bb = reinterpret_cast<const float2*>(b1)[lane];
    float ox = fmaxf(fmaf(di, acc.x + self.x, bb.x), 0.f);
    float oy = fmaxf(fmaf(di, acc.y + self.y, bb.y), 0.f);
    reinterpret_cast<__half2*>(g_x1h)[node * 32 + lane] = __floats2half2_rn(ox, oy);
}

// ---------------- layer-2 agg + scorer: 2 nodes/warp; re-zeroes g_cnt for next replay ----------------
__global__ void agg2_final_kernel(const float* __restrict__ b2, const float* __restrict__ fcw,
                                  const float* __restrict__ fcb, float* __restrict__ out) {
    int warp = blockIdx.x * 8 + (threadIdx.x >> 5);
    int lane = threadIdx.x & 31;
    int half = lane >> 4;
    int hl   = lane & 15;
    int node = warp * 2 + half;
    if (node >= NN) return;
    int beg = g_rows[node], cnt = g_cnt[node];
    const __half2* __restrict__ h = reinterpret_cast<const __half2*>(g_h2s);
    float2 acc = {0.f, 0.f};
    int j = 0;
    for (; j + 4 <= cnt; j += 4) {
        int s0 = g_col[beg + j], s1 = g_col[beg + j + 1];
        int s2 = g_col[beg + j + 2], s3 = g_col[beg + j + 3];
        float2 v0 = __half22float2(h[s0 * 16 + hl]);
        float2 v1 = __half22float2(h[s1 * 16 + hl]);
        float2 v2 = __half22float2(h[s2 * 16 + hl]);
        float2 v3 = __half22float2(h[s3 * 16 + hl]);
        acc.x += (v0.x + v1.x) + (v2.x + v3.x);
        acc.y += (v0.y + v1.y) + (v2.y + v3.y);
    }
    for (; j < cnt; j++) {
        float2 v = __half22float2(h[g_col[beg + j] * 16 + hl]);
        acc.x += v.x; acc.y += v.y;
    }
    float di = g_dinv[node];
    float2 self = __half22float2(h[node * 16 + hl]);
    float2 bb = reinterpret_cast<const float2*>(b2)[hl];
    float2 o;
    o.x = fmaxf(fmaf(di, acc.x + self.x, bb.x), 0.f);
    o.y = fmaxf(fmaf(di, acc.y + self.y, bb.y), 0.f);
    reinterpret_cast<float2*>(out + NN)[node * 16 + hl] = o;
    float2 fw = reinterpret_cast<const float2*>(fcw)[hl];
    float s = o.x * fw.x + o.y * fw.y;
#pragma unroll
    for (int off = 8; off > 0; off >>= 1)
        s += __shfl_down_sync(0xffffffffu, s, off, 16);
    if (hl == 0) {
        out[node] = s + fcb[0];
        g_cnt[node] = 0;            // restore invariant for next graph replay
    }
}

// ---------------- launch ----------------
extern "C" void kernel_launch(void* const* d_in, const int* in_sizes, int n_in,
                              void* d_out, int out_size) {
    const float* x   = (const float*)d_in[0];
    const int*   ei  = (const int*)  d_in[1];
    const float* W1  = (const float*)d_in[2];
    const float* b1  = (const float*)d_in[3];
    const float* W2  = (const float*)d_in[4];
    const float* b2  = (const float*)d_in[5];
    const float* fcw = (const float*)d_in[6];
    const float* fcb = (const float*)d_in[7];
    float* out = (float*)d_out;

    const int* src = ei;
    const int* dst = ei + EE;

    __half *h1s, *h2s, *x1h;
    float *dinv;
    cudaGetSymbolAddress((void**)&h1s,  g_h1s);
    cudaGetSymbolAddress((void**)&x1h,  g_x1h);
    cudaGetSymbolAddress((void**)&h2s,  g_h2s);
    cudaGetSymbolAddress((void**)&dinv, g_dinv);

    static cudaStream_t s2 = [] { cudaStream_t s; cudaStreamCreateWithFlags(&s, cudaStreamNonBlocking); return s; }();
    static cudaEvent_t evH = [] { cudaEvent_t e; cudaEventCreateWithFlags(&e, cudaEventDisableTiming); return e; }();
    static cudaEvent_t evC = [] { cudaEvent_t e; cudaEventCreateWithFlags(&e, cudaEventDisableTiming); return e; }();

    // ---- main stream: hist(+rank) -> dinv -> GEMM1 ----
    hist_kernel<<<(EE + 511) / 512, 512>>>(dst);
    cudaEventRecord(evH, 0);
    dinv_kernel<<<(NN + 255) / 256, 256>>>();

    constexpr int SM1 = (128 * 68 + 2 * DH * (KDIN + 4)) * 4;
    cudaFuncSetAttribute((const void*)gemm_mma<DH, KDIN, false>,
                         cudaFuncAttributeMaxDynamicSharedMemorySize, SM1);
    gemm_mma<DH, KDIN, false><<<(NN + 127) / 128, 256, SM1>>>(x, W1, dinv, h1s, NN);

    // ---- side stream (forked after hist): scan1 -> scan3 -> scatter (atomic-free) ----
    cudaStreamWaitEvent(s2, evH, 0);
    scan1_kernel<<<NB_SCAN, 256, 0, s2>>>();
    scan3_kernel<<<(NN + 255) / 256, 256, 0, s2>>>();
    scatter_kernel<<<(EE + 1023) / 1024, 1024, 0, s2>>>(src, dst);
    cudaEventRecord(evC, s2);

    // ---- join, then agg1 -> GEMM2 -> agg2 ----
    cudaStreamWaitEvent(0, evC, 0);
    agg1_kernel<<<(NN + 7) / 8, 256>>>(b1);

    constexpr int SM2 = (128 * 68 + 2 * DOUT * (DH + 4)) * 4;
    cudaFuncSetAttribute((const void*)gemm_mma<DOUT, DH, true>,
                         cudaFuncAttributeMaxDynamicSharedMemorySize, SM2);
    gemm_mma<DOUT, DH, true><<<(NN + 127) / 128, 256, SM2>>>(x1h, W2, dinv, h2s, NN);
    agg2_final_kernel<<<(NN + 15) / 16, 256>>>(b2, fcw, fcb, out);
    (void)in_sizes; (void)n_in; (void)out_size;
}